// round 14
// baseline (speedup 1.0000x reference)
#include <cuda_runtime.h>
#include <cuda_bf16.h>
#include <math.h>

// Shapes (fixed dataset):
//   x_all: [100000, 256] f32, n_id: [50000] i32, edge_index: [2, 300000] i32
//   W_sage: [256,256] f32, b_sage: [256] f32, W_cls: [3,256] f32, b_cls: [3] f32
//   out: [50000, 3] f32 (log_softmax)
//
// out = log_softmax( mean_j( x[j] @ Wc ) + bc )  (linearity), and log_softmax
// is shift-invariant -> project each node to the 2 score DIFFERENCES vs class 2.
// R14: the per-edge neighbor-count atomic is dst-only -> issue it from k_z's
// prologue (hidden under k_z's DRAM stalls). k_edge = 2 atomic lanes/edge.
// Counts in int scratch g_icnt; k_final reads (+1 self) and RESETS to zero so
// each graph replay enters the invariant zeroed state.
#define NMAX 50000
#define FDIM 256
#define F4   64
#define CCLS 2          // two difference classes

__device__ float  g_Wd  [CCLS * FDIM];   // diff weights
__device__ float  g_bd  [CCLS];          // diff biases
__device__ float2 g_z   [NMAX];          // per-node projected diffs
__device__ float2 g_accd[NMAX];          // accumulated diffs
__device__ int    g_icnt[NMAX];          // edge count per dst (zero-init; reset by k_final)

__device__ __forceinline__ void pdl_wait()    { asm volatile("griddepcontrol.wait;" ::: "memory"); }
__device__ __forceinline__ void pdl_trigger() { asm volatile("griddepcontrol.launch_dependents;" ::: "memory"); }
__device__ __forceinline__ void redg_v2(float2* p, float2 v) {
    asm volatile("red.global.add.v2.f32 [%0], {%1, %2};"
                 :: "l"(p), "f"(v.x), "f"(v.y) : "memory");
}
__device__ __forceinline__ void redg_s32(int* p, int v) {
    asm volatile("red.global.add.s32 [%0], %1;"
                 :: "l"(p), "r"(v) : "memory");
}

// ---------------------------------------------------------------------------
// Kernel 0: parallel fusion of diff weights. One warp per output element.
// ---------------------------------------------------------------------------
__global__ void k_init(const float* __restrict__ W_sage,
                       const float* __restrict__ b_sage,
                       const float* __restrict__ W_cls,
                       const float* __restrict__ b_cls) {
    int gid  = blockIdx.x * blockDim.x + threadIdx.x;
    int ww   = gid >> 5;
    int lane = gid & 31;
    const unsigned full = 0xffffffffu;

    if (ww < CCLS * FDIM) {
        int c = ww >> 8;          // 0 or 1
        int k = ww & 255;
        const float4* wrow = reinterpret_cast<const float4*>(W_sage + k * FDIM);
        const float4* crow = reinterpret_cast<const float4*>(W_cls  + c * FDIM);
        const float4* rrow = reinterpret_cast<const float4*>(W_cls  + 2 * FDIM);
        float4 a0 = __ldg(&wrow[lane]);      float4 a1 = __ldg(&wrow[lane + 32]);
        float4 b0 = __ldg(&crow[lane]);      float4 b1 = __ldg(&crow[lane + 32]);
        float4 r0 = __ldg(&rrow[lane]);      float4 r1 = __ldg(&rrow[lane + 32]);
        float4 e0 = make_float4(b0.x-r0.x, b0.y-r0.y, b0.z-r0.z, b0.w-r0.w);
        float4 e1 = make_float4(b1.x-r1.x, b1.y-r1.y, b1.z-r1.z, b1.w-r1.w);
        float s = fmaf(a0.x, e0.x, fmaf(a0.y, e0.y, fmaf(a0.z, e0.z, a0.w * e0.w)))
                + fmaf(a1.x, e1.x, fmaf(a1.y, e1.y, fmaf(a1.z, e1.z, a1.w * e1.w)));
        #pragma unroll
        for (int off = 16; off > 0; off >>= 1)
            s += __shfl_down_sync(full, s, off);
        if (lane == 0) g_Wd[c * FDIM + k] = s;
    } else if (ww < CCLS * FDIM + CCLS) {
        int c = ww - CCLS * FDIM;
        const float4* brow = reinterpret_cast<const float4*>(b_sage);
        const float4* crow = reinterpret_cast<const float4*>(W_cls + c * FDIM);
        const float4* rrow = reinterpret_cast<const float4*>(W_cls + 2 * FDIM);
        float4 a0 = __ldg(&brow[lane]);      float4 a1 = __ldg(&brow[lane + 32]);
        float4 b0 = __ldg(&crow[lane]);      float4 b1 = __ldg(&crow[lane + 32]);
        float4 r0 = __ldg(&rrow[lane]);      float4 r1 = __ldg(&rrow[lane + 32]);
        float4 e0 = make_float4(b0.x-r0.x, b0.y-r0.y, b0.z-r0.z, b0.w-r0.w);
        float4 e1 = make_float4(b1.x-r1.x, b1.y-r1.y, b1.z-r1.z, b1.w-r1.w);
        float s = fmaf(a0.x, e0.x, fmaf(a0.y, e0.y, fmaf(a0.z, e0.z, a0.w * e0.w)))
                + fmaf(a1.x, e1.x, fmaf(a1.y, e1.y, fmaf(a1.z, e1.z, a1.w * e1.w)));
        #pragma unroll
        for (int off = 16; off > 0; off >>= 1)
            s += __shfl_down_sync(full, s, off);
        if (lane == 0) g_bd[c] = s + __ldg(&b_cls[c]) - __ldg(&b_cls[2]);
    }
    pdl_trigger();
}

// ---------------------------------------------------------------------------
// Kernel 1: project (4 nodes/warp) + HOISTED degree count (1 edge/thread).
//   z[i] = x_all[n_id[i]] @ Wd (2 floats);  accd[i] = z[i]
//   g_icnt[dst[e]] += 1   (hidden under the DRAM-bound row fetches)
// ---------------------------------------------------------------------------
__global__ void k_z(const float4* __restrict__ x_all4,
                    const int* __restrict__ n_id,
                    const int* __restrict__ dst, int N, int E) {
    __shared__ float sW[CCLS][FDIM];
    int t    = threadIdx.x;
    int gtid = blockIdx.x * blockDim.x + t;
    int wp   = gtid >> 5;
    int lane = t & 31;
    int w0 = wp * 4;

    // hoisted degree count: one edge per thread (grid threads >= E here;
    // previous replay's k_final has fully completed -> g_icnt is zeroed)
    if (gtid < E) {
        int d = __ldg(&dst[gtid]);
        redg_s32(&g_icnt[d], 1);
    }

    float4 d0a, d0b, d1a, d1b, d2a, d2b, d3a, d3b;
    const float4 Z = make_float4(0.f, 0.f, 0.f, 0.f);
    d0a = d0b = d1a = d1b = d2a = d2b = d3a = d3b = Z;
    bool h0 = (w0     < N);
    bool h1 = (w0 + 1 < N);
    bool h2 = (w0 + 2 < N);
    bool h3 = (w0 + 3 < N);
    if (h0) {
        const float4* xp = x_all4 + (long long)__ldg(&n_id[w0]) * F4;
        d0a = __ldg(&xp[lane]); d0b = __ldg(&xp[lane + 32]);
    }
    if (h1) {
        const float4* xp = x_all4 + (long long)__ldg(&n_id[w0 + 1]) * F4;
        d1a = __ldg(&xp[lane]); d1b = __ldg(&xp[lane + 32]);
    }
    if (h2) {
        const float4* xp = x_all4 + (long long)__ldg(&n_id[w0 + 2]) * F4;
        d2a = __ldg(&xp[lane]); d2b = __ldg(&xp[lane + 32]);
    }
    if (h3) {
        const float4* xp = x_all4 + (long long)__ldg(&n_id[w0 + 3]) * F4;
        d3a = __ldg(&xp[lane]); d3b = __ldg(&xp[lane + 32]);
    }

    pdl_wait();   // g_Wd ready
    for (int idx = t; idx < CCLS * FDIM; idx += blockDim.x)
        sW[idx >> 8][idx & 255] = g_Wd[idx];
    __syncthreads();

    if (!h0) { pdl_trigger(); return; }

    int k0 = lane * 4, k1 = (lane + 32) * 4;
    float w00 = sW[0][k0], w01 = sW[0][k0+1], w02 = sW[0][k0+2], w03 = sW[0][k0+3];
    float w10 = sW[1][k0], w11 = sW[1][k0+1], w12 = sW[1][k0+2], w13 = sW[1][k0+3];
    float v00 = sW[0][k1], v01 = sW[0][k1+1], v02 = sW[0][k1+2], v03 = sW[0][k1+3];
    float v10 = sW[1][k1], v11 = sW[1][k1+1], v12 = sW[1][k1+2], v13 = sW[1][k1+3];

    #define DOT2(ra, rb, o0, o1)                                                \
        o0 = fmaf((ra).x,w00, fmaf((ra).y,w01, fmaf((ra).z,w02, (ra).w*w03)));  \
        o1 = fmaf((ra).x,w10, fmaf((ra).y,w11, fmaf((ra).z,w12, (ra).w*w13)));  \
        o0 = fmaf((rb).x,v00, fmaf((rb).y,v01, fmaf((rb).z,v02, fmaf((rb).w,v03, o0)))); \
        o1 = fmaf((rb).x,v10, fmaf((rb).y,v11, fmaf((rb).z,v12, fmaf((rb).w,v13, o1))));

    float x0, x1, y0, y1, u0, u1, q0, q1;
    DOT2(d0a, d0b, x0, x1)
    DOT2(d1a, d1b, y0, y1)
    DOT2(d2a, d2b, u0, u1)
    DOT2(d3a, d3b, q0, q1)
    #undef DOT2

    const unsigned full = 0xffffffffu;
    #pragma unroll
    for (int off = 16; off > 0; off >>= 1) {
        x0 += __shfl_down_sync(full, x0, off);
        x1 += __shfl_down_sync(full, x1, off);
        y0 += __shfl_down_sync(full, y0, off);
        y1 += __shfl_down_sync(full, y1, off);
        u0 += __shfl_down_sync(full, u0, off);
        u1 += __shfl_down_sync(full, u1, off);
        q0 += __shfl_down_sync(full, q0, off);
        q1 += __shfl_down_sync(full, q1, off);
    }
    if (lane == 0) {
        float2 zv = make_float2(x0, x1);
        g_z[w0] = zv;  g_accd[w0] = zv;
        if (h1) { float2 v = make_float2(y0, y1); g_z[w0+1] = v; g_accd[w0+1] = v; }
        if (h2) { float2 v = make_float2(u0, u1); g_z[w0+2] = v; g_accd[w0+2] = v; }
        if (h3) { float2 v = make_float2(q0, q1); g_z[w0+3] = v; g_accd[w0+3] = v; }
    }
    pdl_trigger();
}

// ---------------------------------------------------------------------------
// Kernel 2: edge aggregation. FOUR edges per thread, 2 atomic lanes/edge.
// ---------------------------------------------------------------------------
__global__ void k_edge(const int* __restrict__ src,
                       const int* __restrict__ dst, int E) {
    int q  = blockIdx.x * blockDim.x + threadIdx.x;
    int e0 = q * 4;
    if (e0 >= E) { pdl_wait(); pdl_trigger(); return; }

    if (e0 + 3 < E) {
        int4 sv = __ldg(reinterpret_cast<const int4*>(src) + q);
        int4 dv = __ldg(reinterpret_cast<const int4*>(dst) + q);
        pdl_wait();   // g_z / g_accd ready
        float2 v0 = __ldg(&g_z[sv.x]);
        float2 v1 = __ldg(&g_z[sv.y]);
        float2 v2 = __ldg(&g_z[sv.z]);
        float2 v3 = __ldg(&g_z[sv.w]);
        redg_v2(&g_accd[dv.x], v0);
        redg_v2(&g_accd[dv.y], v1);
        redg_v2(&g_accd[dv.z], v2);
        redg_v2(&g_accd[dv.w], v3);
    } else {
        pdl_wait();
        for (int e = e0; e < E; e++) {
            int s = __ldg(&src[e]);
            int d = __ldg(&dst[e]);
            redg_v2(&g_accd[d], __ldg(&g_z[s]));
        }
    }
    pdl_trigger();
}

// ---------------------------------------------------------------------------
// Kernel 3: finalize. Two nodes per thread.
//   cnt = icnt+1 (self loop);  g_c = accd_c/cnt + bd_c
//   out2 = -lse(g0,g1,0);  out_c = g_c + out2
// Resets g_icnt to zero for the next graph replay.
// ---------------------------------------------------------------------------
__global__ void k_final(float* __restrict__ out, int N) {
    int p  = blockIdx.x * blockDim.x + threadIdx.x;
    int i0 = p * 2;
    pdl_wait();   // all REDG visible
    if (i0 >= N) return;
    int i1 = i0 + 1;
    bool has1 = (i1 < N);

    float2 a  = g_accd[i0];
    int    c0 = g_icnt[i0];
    g_icnt[i0] = 0;                          // restore invariant for next replay
    float2 b  = has1 ? g_accd[i1] : make_float2(0.f, 0.f);
    int    c1 = 0;
    if (has1) { c1 = g_icnt[i1]; g_icnt[i1] = 0; }
    float bd0 = g_bd[0], bd1 = g_bd[1];

    float inva = __frcp_rn((float)(c0 + 1));
    float invb = __frcp_rn((float)(c1 + 1));
    float ag0 = fmaf(a.x, inva, bd0), bg0 = fmaf(b.x, invb, bd0);
    float ag1 = fmaf(a.y, inva, bd1), bg1 = fmaf(b.y, invb, bd1);

    float am = fmaxf(0.0f, fmaxf(ag0, ag1));
    float bm = fmaxf(0.0f, fmaxf(bg0, bg1));
    float alse = am + __logf(__expf(ag0 - am) + __expf(ag1 - am) + __expf(-am));
    float blse = bm + __logf(__expf(bg0 - bm) + __expf(bg1 - bm) + __expf(-bm));

    out[i0 * 3 + 0] = ag0 - alse;
    out[i0 * 3 + 1] = ag1 - alse;
    out[i0 * 3 + 2] = -alse;
    if (has1) {
        out[i1 * 3 + 0] = bg0 - blse;
        out[i1 * 3 + 1] = bg1 - blse;
        out[i1 * 3 + 2] = -blse;
    }
}

// ---------------------------------------------------------------------------
static inline void launch_pdl(void* fn, dim3 grid, dim3 block,
                              void** args, bool pdl_in) {
    cudaLaunchConfig_t cfg = {};
    cfg.gridDim  = grid;
    cfg.blockDim = block;
    cfg.dynamicSmemBytes = 0;
    cfg.stream = 0;
    cudaLaunchAttribute attr[1];
    int nattr = 0;
    if (pdl_in) {
        attr[0].id = cudaLaunchAttributeProgrammaticStreamSerialization;
        attr[0].val.programmaticStreamSerializationAllowed = 1;
        nattr = 1;
    }
    cfg.attrs = attr;
    cfg.numAttrs = nattr;
    cudaLaunchKernelExC(&cfg, fn, args);
}

extern "C" void kernel_launch(void* const* d_in, const int* in_sizes, int n_in,
                              void* d_out, int out_size) {
    const float* x_all  = (const float*)d_in[0];
    const int*   n_id   = (const int*)  d_in[1];
    const int*   eidx   = (const int*)  d_in[2];
    const float* W_sage = (const float*)d_in[3];
    const float* b_sage = (const float*)d_in[4];
    const float* W_cls  = (const float*)d_in[5];
    const float* b_cls  = (const float*)d_in[6];
    float* out = (float*)d_out;

    int N = in_sizes[1];          // 50000
    int E = in_sizes[2] / 2;      // 300000
    const int* src = eidx;        // edge_index[0, :]
    const int* dst = eidx + E;    // edge_index[1, :]

    // k_init: 514 warp-tasks
    {
        int threads = (CCLS * FDIM + CCLS) * 32;
        dim3 g((threads + 255) / 256), b(256);
        void* args[] = {(void*)&W_sage, (void*)&b_sage, (void*)&W_cls, (void*)&b_cls};
        launch_pdl((void*)k_init, g, b, args, false);
    }
    // k_z: FOUR nodes per warp (threads = 400K >= E, covers degree counting)
    {
        const float4* x4 = reinterpret_cast<const float4*>(x_all);
        int warps = (N + 3) / 4;
        long long th = (long long)warps * 32;
        dim3 g((unsigned)((th + 255) / 256)), b(256);
        void* args[] = {(void*)&x4, (void*)&n_id, (void*)&dst, (void*)&N, (void*)&E};
        launch_pdl((void*)k_z, g, b, args, true);
    }
    // k_edge: four edges per thread
    {
        int quads = (E + 3) / 4;
        dim3 g((quads + 255) / 256), b(256);
        void* args[] = {(void*)&src, (void*)&dst, (void*)&E};
        launch_pdl((void*)k_edge, g, b, args, true);
    }
    // k_final: two nodes per thread, block=128
    {
        int pairs = (N + 1) / 2;
        dim3 g((pairs + 127) / 128), b(128);
        void* args[] = {(void*)&out, (void*)&N};
        launch_pdl((void*)k_final, g, b, args, true);
    }
}

// round 15
// speedup vs baseline: 1.0084x; 1.0084x over previous
#include <cuda_runtime.h>
#include <cuda_bf16.h>
#include <math.h>

// Shapes (fixed dataset):
//   x_all: [100000, 256] f32, n_id: [50000] i32, edge_index: [2, 300000] i32
//   W_sage: [256,256] f32, b_sage: [256] f32, W_cls: [3,256] f32, b_cls: [3] f32
//   out: [50000, 3] f32 (log_softmax)
//
// out = log_softmax( mean_j( x[j] @ Wc ) + bc )  (linearity); shift-invariance
// -> project each node to the 2 score DIFFERENCES vs class 2 (R13 structure).
// R15: cross-replay PDL — k_final triggers after its reads, k_init carries the
// PDL attribute, so replay i+1's weight fusion runs under replay i's epilogue.
#define NMAX 50000
#define FDIM 256
#define F4   64
#define CCLS 2          // two difference classes

__device__ float  g_Wd  [CCLS * FDIM];   // diff weights
__device__ float  g_bd  [CCLS];          // diff biases
__device__ float2 g_z   [NMAX];          // per-node projected diffs
__device__ float2 g_accd[NMAX];          // accumulated diffs
__device__ float  g_cnt [NMAX];          // neighbor count incl. self

__device__ __forceinline__ void pdl_wait()    { asm volatile("griddepcontrol.wait;" ::: "memory"); }
__device__ __forceinline__ void pdl_trigger() { asm volatile("griddepcontrol.launch_dependents;" ::: "memory"); }
__device__ __forceinline__ void redg_v2(float2* p, float2 v) {
    asm volatile("red.global.add.v2.f32 [%0], {%1, %2};"
                 :: "l"(p), "f"(v.x), "f"(v.y) : "memory");
}
__device__ __forceinline__ void redg_f32(float* p, float v) {
    asm volatile("red.global.add.f32 [%0], %1;"
                 :: "l"(p), "f"(v) : "memory");
}

// ---------------------------------------------------------------------------
// Kernel 0: parallel fusion of diff weights. One warp per output element.
//   Wd[c][k] = sum_h W_sage[k,h] * (W_cls[c,h] - W_cls[2,h])   c in {0,1}
// Identical-value rewrite each replay -> benign overlap with k_final(i).
// ---------------------------------------------------------------------------
__global__ void k_init(const float* __restrict__ W_sage,
                       const float* __restrict__ b_sage,
                       const float* __restrict__ W_cls,
                       const float* __restrict__ b_cls) {
    int gid  = blockIdx.x * blockDim.x + threadIdx.x;
    int ww   = gid >> 5;
    int lane = gid & 31;
    const unsigned full = 0xffffffffu;

    if (ww < CCLS * FDIM) {
        int c = ww >> 8;          // 0 or 1
        int k = ww & 255;
        const float4* wrow = reinterpret_cast<const float4*>(W_sage + k * FDIM);
        const float4* crow = reinterpret_cast<const float4*>(W_cls  + c * FDIM);
        const float4* rrow = reinterpret_cast<const float4*>(W_cls  + 2 * FDIM);
        float4 a0 = __ldg(&wrow[lane]);      float4 a1 = __ldg(&wrow[lane + 32]);
        float4 b0 = __ldg(&crow[lane]);      float4 b1 = __ldg(&crow[lane + 32]);
        float4 r0 = __ldg(&rrow[lane]);      float4 r1 = __ldg(&rrow[lane + 32]);
        float4 e0 = make_float4(b0.x-r0.x, b0.y-r0.y, b0.z-r0.z, b0.w-r0.w);
        float4 e1 = make_float4(b1.x-r1.x, b1.y-r1.y, b1.z-r1.z, b1.w-r1.w);
        float s = fmaf(a0.x, e0.x, fmaf(a0.y, e0.y, fmaf(a0.z, e0.z, a0.w * e0.w)))
                + fmaf(a1.x, e1.x, fmaf(a1.y, e1.y, fmaf(a1.z, e1.z, a1.w * e1.w)));
        #pragma unroll
        for (int off = 16; off > 0; off >>= 1)
            s += __shfl_down_sync(full, s, off);
        if (lane == 0) g_Wd[c * FDIM + k] = s;
    } else if (ww < CCLS * FDIM + CCLS) {
        int c = ww - CCLS * FDIM;
        const float4* brow = reinterpret_cast<const float4*>(b_sage);
        const float4* crow = reinterpret_cast<const float4*>(W_cls + c * FDIM);
        const float4* rrow = reinterpret_cast<const float4*>(W_cls + 2 * FDIM);
        float4 a0 = __ldg(&brow[lane]);      float4 a1 = __ldg(&brow[lane + 32]);
        float4 b0 = __ldg(&crow[lane]);      float4 b1 = __ldg(&crow[lane + 32]);
        float4 r0 = __ldg(&rrow[lane]);      float4 r1 = __ldg(&rrow[lane + 32]);
        float4 e0 = make_float4(b0.x-r0.x, b0.y-r0.y, b0.z-r0.z, b0.w-r0.w);
        float4 e1 = make_float4(b1.x-r1.x, b1.y-r1.y, b1.z-r1.z, b1.w-r1.w);
        float s = fmaf(a0.x, e0.x, fmaf(a0.y, e0.y, fmaf(a0.z, e0.z, a0.w * e0.w)))
                + fmaf(a1.x, e1.x, fmaf(a1.y, e1.y, fmaf(a1.z, e1.z, a1.w * e1.w)));
        #pragma unroll
        for (int off = 16; off > 0; off >>= 1)
            s += __shfl_down_sync(full, s, off);
        if (lane == 0) g_bd[c] = s + __ldg(&b_cls[c]) - __ldg(&b_cls[2]);
    }
    pdl_trigger();
}

// ---------------------------------------------------------------------------
// Kernel 1: project, FOUR nodes per warp (8 independent LDG.128/lane pre-wait).
//   z[i] = x_all[n_id[i]] @ Wd (2 floats);  accd[i] = z[i]; cnt[i] = 1
// ---------------------------------------------------------------------------
__global__ void k_z(const float4* __restrict__ x_all4,
                    const int* __restrict__ n_id, int N) {
    __shared__ float sW[CCLS][FDIM];
    int t    = threadIdx.x;
    int wp   = (blockIdx.x * blockDim.x + t) >> 5;
    int lane = t & 31;
    int w0 = wp * 4;

    float4 d0a, d0b, d1a, d1b, d2a, d2b, d3a, d3b;
    const float4 Z = make_float4(0.f, 0.f, 0.f, 0.f);
    d0a = d0b = d1a = d1b = d2a = d2b = d3a = d3b = Z;
    bool h0 = (w0     < N);
    bool h1 = (w0 + 1 < N);
    bool h2 = (w0 + 2 < N);
    bool h3 = (w0 + 3 < N);
    if (h0) {
        const float4* xp = x_all4 + (long long)__ldg(&n_id[w0]) * F4;
        d0a = __ldg(&xp[lane]); d0b = __ldg(&xp[lane + 32]);
    }
    if (h1) {
        const float4* xp = x_all4 + (long long)__ldg(&n_id[w0 + 1]) * F4;
        d1a = __ldg(&xp[lane]); d1b = __ldg(&xp[lane + 32]);
    }
    if (h2) {
        const float4* xp = x_all4 + (long long)__ldg(&n_id[w0 + 2]) * F4;
        d2a = __ldg(&xp[lane]); d2b = __ldg(&xp[lane + 32]);
    }
    if (h3) {
        const float4* xp = x_all4 + (long long)__ldg(&n_id[w0 + 3]) * F4;
        d3a = __ldg(&xp[lane]); d3b = __ldg(&xp[lane + 32]);
    }

    pdl_wait();   // g_Wd ready
    for (int idx = t; idx < CCLS * FDIM; idx += blockDim.x)
        sW[idx >> 8][idx & 255] = g_Wd[idx];
    __syncthreads();

    if (!h0) { pdl_trigger(); return; }

    int k0 = lane * 4, k1 = (lane + 32) * 4;
    float w00 = sW[0][k0], w01 = sW[0][k0+1], w02 = sW[0][k0+2], w03 = sW[0][k0+3];
    float w10 = sW[1][k0], w11 = sW[1][k0+1], w12 = sW[1][k0+2], w13 = sW[1][k0+3];
    float v00 = sW[0][k1], v01 = sW[0][k1+1], v02 = sW[0][k1+2], v03 = sW[0][k1+3];
    float v10 = sW[1][k1], v11 = sW[1][k1+1], v12 = sW[1][k1+2], v13 = sW[1][k1+3];

    #define DOT2(ra, rb, o0, o1)                                                \
        o0 = fmaf((ra).x,w00, fmaf((ra).y,w01, fmaf((ra).z,w02, (ra).w*w03)));  \
        o1 = fmaf((ra).x,w10, fmaf((ra).y,w11, fmaf((ra).z,w12, (ra).w*w13)));  \
        o0 = fmaf((rb).x,v00, fmaf((rb).y,v01, fmaf((rb).z,v02, fmaf((rb).w,v03, o0)))); \
        o1 = fmaf((rb).x,v10, fmaf((rb).y,v11, fmaf((rb).z,v12, fmaf((rb).w,v13, o1))));

    float x0, x1, y0, y1, u0, u1, q0, q1;
    DOT2(d0a, d0b, x0, x1)
    DOT2(d1a, d1b, y0, y1)
    DOT2(d2a, d2b, u0, u1)
    DOT2(d3a, d3b, q0, q1)
    #undef DOT2

    const unsigned full = 0xffffffffu;
    #pragma unroll
    for (int off = 16; off > 0; off >>= 1) {
        x0 += __shfl_down_sync(full, x0, off);
        x1 += __shfl_down_sync(full, x1, off);
        y0 += __shfl_down_sync(full, y0, off);
        y1 += __shfl_down_sync(full, y1, off);
        u0 += __shfl_down_sync(full, u0, off);
        u1 += __shfl_down_sync(full, u1, off);
        q0 += __shfl_down_sync(full, q0, off);
        q1 += __shfl_down_sync(full, q1, off);
    }
    if (lane == 0) {
        float2 zv = make_float2(x0, x1);
        g_z[w0] = zv;  g_accd[w0] = zv;  g_cnt[w0] = 1.0f;
        if (h1) { float2 v = make_float2(y0, y1); g_z[w0+1] = v; g_accd[w0+1] = v; g_cnt[w0+1] = 1.0f; }
        if (h2) { float2 v = make_float2(u0, u1); g_z[w0+2] = v; g_accd[w0+2] = v; g_cnt[w0+2] = 1.0f; }
        if (h3) { float2 v = make_float2(q0, q1); g_z[w0+3] = v; g_accd[w0+3] = v; g_cnt[w0+3] = 1.0f; }
    }
    pdl_trigger();
}

// ---------------------------------------------------------------------------
// Kernel 2: edge aggregation. FOUR edges per thread.
//   accd[dst] += z[src]  (REDG v2) ;  cnt[dst] += 1  (REDG f32)
// ---------------------------------------------------------------------------
__global__ void k_edge(const int* __restrict__ src,
                       const int* __restrict__ dst, int E) {
    int q  = blockIdx.x * blockDim.x + threadIdx.x;
    int e0 = q * 4;
    if (e0 >= E) { pdl_wait(); pdl_trigger(); return; }

    if (e0 + 3 < E) {
        int4 sv = __ldg(reinterpret_cast<const int4*>(src) + q);
        int4 dv = __ldg(reinterpret_cast<const int4*>(dst) + q);
        pdl_wait();   // g_z / g_accd / g_cnt ready
        float2 v0 = __ldg(&g_z[sv.x]);
        float2 v1 = __ldg(&g_z[sv.y]);
        float2 v2 = __ldg(&g_z[sv.z]);
        float2 v3 = __ldg(&g_z[sv.w]);
        redg_v2(&g_accd[dv.x], v0);
        redg_v2(&g_accd[dv.y], v1);
        redg_v2(&g_accd[dv.z], v2);
        redg_v2(&g_accd[dv.w], v3);
        redg_f32(&g_cnt[dv.x], 1.0f);
        redg_f32(&g_cnt[dv.y], 1.0f);
        redg_f32(&g_cnt[dv.z], 1.0f);
        redg_f32(&g_cnt[dv.w], 1.0f);
    } else {
        pdl_wait();
        for (int e = e0; e < E; e++) {
            int s = __ldg(&src[e]);
            int d = __ldg(&dst[e]);
            redg_v2(&g_accd[d], __ldg(&g_z[s]));
            redg_f32(&g_cnt[d], 1.0f);
        }
    }
    pdl_trigger();
}

// ---------------------------------------------------------------------------
// Kernel 3: finalize. Two nodes per thread. Triggers the NEXT REPLAY's k_init
// right after its global reads (before softmax + stores) -> cross-replay
// overlap of the weight fusion with this kernel's epilogue.
// ---------------------------------------------------------------------------
__global__ void k_final(float* __restrict__ out, int N) {
    int p  = blockIdx.x * blockDim.x + threadIdx.x;
    int i0 = p * 2;
    pdl_wait();   // all REDG visible
    if (i0 >= N) return;   // exited CTAs count toward dependent-launch condition
    int i1 = i0 + 1;
    bool has1 = (i1 < N);

    float2 a  = g_accd[i0];
    float  ac = g_cnt[i0];
    float2 b  = has1 ? g_accd[i1] : make_float2(0.f, 0.f);
    float  bcnt = has1 ? g_cnt[i1] : 1.0f;
    float bd0 = g_bd[0], bd1 = g_bd[1];

    pdl_trigger();   // all global reads done -> next replay's k_init may start

    float inva = __frcp_rn(ac);
    float invb = __frcp_rn(bcnt);
    float ag0 = fmaf(a.x, inva, bd0), bg0 = fmaf(b.x, invb, bd0);
    float ag1 = fmaf(a.y, inva, bd1), bg1 = fmaf(b.y, invb, bd1);

    float am = fmaxf(0.0f, fmaxf(ag0, ag1));
    float bm = fmaxf(0.0f, fmaxf(bg0, bg1));
    float alse = am + __logf(__expf(ag0 - am) + __expf(ag1 - am) + __expf(-am));
    float blse = bm + __logf(__expf(bg0 - bm) + __expf(bg1 - bm) + __expf(-bm));

    out[i0 * 3 + 0] = ag0 - alse;
    out[i0 * 3 + 1] = ag1 - alse;
    out[i0 * 3 + 2] = -alse;
    if (has1) {
        out[i1 * 3 + 0] = bg0 - blse;
        out[i1 * 3 + 1] = bg1 - blse;
        out[i1 * 3 + 2] = -blse;
    }
}

// ---------------------------------------------------------------------------
static inline void launch_pdl(void* fn, dim3 grid, dim3 block,
                              void** args, bool pdl_in) {
    cudaLaunchConfig_t cfg = {};
    cfg.gridDim  = grid;
    cfg.blockDim = block;
    cfg.dynamicSmemBytes = 0;
    cfg.stream = 0;
    cudaLaunchAttribute attr[1];
    int nattr = 0;
    if (pdl_in) {
        attr[0].id = cudaLaunchAttributeProgrammaticStreamSerialization;
        attr[0].val.programmaticStreamSerializationAllowed = 1;
        nattr = 1;
    }
    cfg.attrs = attr;
    cfg.numAttrs = nattr;
    cudaLaunchKernelExC(&cfg, fn, args);
}

extern "C" void kernel_launch(void* const* d_in, const int* in_sizes, int n_in,
                              void* d_out, int out_size) {
    const float* x_all  = (const float*)d_in[0];
    const int*   n_id   = (const int*)  d_in[1];
    const int*   eidx   = (const int*)  d_in[2];
    const float* W_sage = (const float*)d_in[3];
    const float* b_sage = (const float*)d_in[4];
    const float* W_cls  = (const float*)d_in[5];
    const float* b_cls  = (const float*)d_in[6];
    float* out = (float*)d_out;

    int N = in_sizes[1];          // 50000
    int E = in_sizes[2] / 2;      // 300000
    const int* src = eidx;        // edge_index[0, :]
    const int* dst = eidx + E;    // edge_index[1, :]

    // k_init: 514 warp-tasks; PDL attr -> overlaps previous replay's k_final
    {
        int threads = (CCLS * FDIM + CCLS) * 32;
        dim3 g((threads + 255) / 256), b(256);
        void* args[] = {(void*)&W_sage, (void*)&b_sage, (void*)&W_cls, (void*)&b_cls};
        launch_pdl((void*)k_init, g, b, args, true);
    }
    // k_z: FOUR nodes per warp
    {
        const float4* x4 = reinterpret_cast<const float4*>(x_all);
        int warps = (N + 3) / 4;
        long long th = (long long)warps * 32;
        dim3 g((unsigned)((th + 255) / 256)), b(256);
        void* args[] = {(void*)&x4, (void*)&n_id, (void*)&N};
        launch_pdl((void*)k_z, g, b, args, true);
    }
    // k_edge: four edges per thread
    {
        int quads = (E + 3) / 4;
        dim3 g((quads + 255) / 256), b(256);
        void* args[] = {(void*)&src, (void*)&dst, (void*)&E};
        launch_pdl((void*)k_edge, g, b, args, true);
    }
    // k_final: two nodes per thread, block=128
    {
        int pairs = (N + 1) / 2;
        dim3 g((pairs + 127) / 128), b(128);
        void* args[] = {(void*)&out, (void*)&N};
        launch_pdl((void*)k_final, g, b, args, true);
    }
}